// round 16
// baseline (speedup 1.0000x reference)
#include <cuda_runtime.h>
#include <cuda_fp16.h>
#include <math.h>
#include <stdint.h>

#define T_TOK 2048
#define NL    12
#define DM    768
#define FL    2048

#define DBN 128
#define DBK 32
#define ASTR 40
#define BSTR 136
#define SB (DBK * BSTR)   // 4352 halves per B stage (encode)

#define DM2 128
#define SA2 (DM2 * ASTR)  // 5120 halves per A stage (encode)

// decode: k-tile 64, A stride 72
#define DBK2 64
#define ASTR2 72
#define SA2D (DM2 * ASTR2)      // 9216 halves per A stage
#define SBD  (DBK2 * BSTR)      // 8704 halves per B stage
#define DEC_B_BASE (3 * SA2D)
#define SMEM_DEC_BYTES ((3 * SA2D + 3 * SBD) * 2)       // 107520

// encode smem (halves): XH, XL (3 stages each), WH (3 stages)
#define EXH_BASE 0
#define EXL_BASE (3 * SA2)
#define EWH_BASE (6 * SA2)
#define SMEM_ENC_BYTES ((6 * SA2 + 3 * SB) * 2)         // 87552

#define NWD 78
#define ENC_BLOCKS (16 * 16 * NL)   // 3072

#define FIX_CAP (1 << 22)
#define DELTA 8e-4f

__device__ __half g_wd16[(size_t)NL * NL * FL * DM];
__device__ __half g_ah[(size_t)T_TOK * NL * FL];
__device__ __half g_xh[(size_t)T_TOK * NL * DM];
__device__ __half g_xl[(size_t)T_TOK * NL * DM];
__device__ __half g_weh[(size_t)NL * DM * FL];
__device__ float  g_weT[(size_t)NL * FL * DM];
__device__ float  g_acts_scratch[(size_t)T_TOK * NL * FL];
__device__ int    g_fix_count;
__device__ int    g_fix_list[FIX_CAP];

// ---------------- helpers ----------------
__device__ __forceinline__ uint32_t smem_u32(const void* p) {
    return (uint32_t)__cvta_generic_to_shared(p);
}
__device__ __forceinline__ void cp16(uint32_t d, const void* s) {
    asm volatile("cp.async.cg.shared.global [%0], [%1], 16;" :: "r"(d), "l"(s));
}
__device__ __forceinline__ void ldsm_x4(uint32_t* r, uint32_t a) {
    asm volatile("ldmatrix.sync.aligned.m8n8.x4.shared.b16 {%0,%1,%2,%3}, [%4];"
                 : "=r"(r[0]), "=r"(r[1]), "=r"(r[2]), "=r"(r[3]) : "r"(a));
}
__device__ __forceinline__ void ldsm_x4t(uint32_t* r, uint32_t a) {
    asm volatile("ldmatrix.sync.aligned.m8n8.x4.trans.shared.b16 {%0,%1,%2,%3}, [%4];"
                 : "=r"(r[0]), "=r"(r[1]), "=r"(r[2]), "=r"(r[3]) : "r"(a));
}
__device__ __forceinline__ void mma_f16(float* d, const uint32_t* a, const uint32_t* b) {
    asm volatile(
        "mma.sync.aligned.m16n8k16.row.col.f32.f16.f16.f32 "
        "{%0,%1,%2,%3}, {%4,%5,%6,%7}, {%8,%9}, {%0,%1,%2,%3};"
        : "+f"(d[0]), "+f"(d[1]), "+f"(d[2]), "+f"(d[3])
        : "r"(a[0]), "r"(a[1]), "r"(a[2]), "r"(a[3]), "r"(b[0]), "r"(b[1]));
}
__device__ __forceinline__ void cvt4(__half* h4, float4 v) {
    h4[0] = __float2half_rn(v.x); h4[1] = __float2half_rn(v.y);
    h4[2] = __float2half_rn(v.z); h4[3] = __float2half_rn(v.w);
}

// ---------------- prep ----------------
#define NB_X  (T_TOK * NL * DM / 1024)
#define NB_TR (NL * (DM / 32) * (FL / 32))
#define NB_PREP (2 * NB_X + NB_TR)

__global__ __launch_bounds__(256)
void prep_xwe(const float* __restrict__ x, const float* __restrict__ we,
              __half* __restrict__ xh, __half* __restrict__ xl,
              __half* __restrict__ weh, float* __restrict__ weT) {
    const int b = blockIdx.x;
    if (b == 0 && threadIdx.x == 0) g_fix_count = 0;

    if (b < NB_X) {
        const size_t idx = ((size_t)b * 256 + threadIdx.x) * 4;
        float4 v = *(const float4*)(x + idx);
        __half h4[4]; cvt4(h4, v);
        __half l4[4] = {__float2half_rn(v.x - __half2float(h4[0])),
                        __float2half_rn(v.y - __half2float(h4[1])),
                        __float2half_rn(v.z - __half2float(h4[2])),
                        __float2half_rn(v.w - __half2float(h4[3]))};
        *(uint2*)(xh + idx) = *(uint2*)h4;
        *(uint2*)(xl + idx) = *(uint2*)l4;
    } else if (b < 2 * NB_X) {
        const size_t idx = ((size_t)(b - NB_X) * 256 + threadIdx.x) * 4;
        float4 v = *(const float4*)(we + idx);
        __half h4[4]; cvt4(h4, v);
        *(uint2*)(weh + idx) = *(uint2*)h4;
    } else {
        __shared__ float t[32][33];
        const int bt = b - 2 * NB_X;
        const int l  = bt / ((DM / 32) * (FL / 32));
        const int rm = bt % ((DM / 32) * (FL / 32));
        const int d0 = (rm / (FL / 32)) * 32;
        const int f0 = (rm % (FL / 32)) * 32;
        const int tx = threadIdx.x & 31, ty = threadIdx.x >> 5;
        const float* src = we + (size_t)l * DM * FL;
        float* dst = weT + (size_t)l * FL * DM;
#pragma unroll
        for (int r = 0; r < 32; r += 8)
            t[ty + r][tx] = src[(size_t)(d0 + ty + r) * FL + f0 + tx];
        __syncthreads();
#pragma unroll
        for (int r = 0; r < 32; r += 8)
            dst[(size_t)(f0 + ty + r) * DM + d0 + tx] = t[tx][ty + r];
    }
}

// ---------------- encode: 512 thr, 16 warps, warp 32x32, 2 CTA/SM -----------
__global__ __launch_bounds__(512, 2)
void encode_fused(const __half* __restrict__ XHp, const __half* __restrict__ XLp,
                  const __half* __restrict__ WHp,
                  const float* __restrict__ TH, float* __restrict__ H,
                  float* __restrict__ A, __half* __restrict__ AH16,
                  const float* __restrict__ WDsrc, __half* __restrict__ WD16) {
    if (blockIdx.x < NWD) {
        const int p = blockIdx.x;
        int i = 0, rem = p;
        while (rem >= NL - i) { rem -= NL - i; i++; }
        const size_t zoff = (size_t)(i * NL + i + rem) * FL * DM;
        const float4* src = (const float4*)(WDsrc + zoff);
        uint2* dst = (uint2*)(WD16 + zoff);
        const int N4 = FL * DM / 4;
        for (int q = threadIdx.x; q < N4; q += 1024) {
            float4 v0 = src[q], v1 = src[q + 512];
            __half h0[4], h1[4];
            cvt4(h0, v0); cvt4(h1, v1);
            dst[q]       = *(uint2*)h0;
            dst[q + 512] = *(uint2*)h1;
        }
        return;
    }

    extern __shared__ __half sm[];
    const uint32_t sb = smem_u32(sm);

    const int bid = blockIdx.x - NWD;
    const int l  = bid >> 8;
    const int bm = ((bid >> 4) & 15) * DM2;
    const int bn = (bid & 15) * DBN;
    const int KT = DM / DBK;   // 24

    const int tid  = threadIdx.x;
    const int lane = tid & 31, wid = tid >> 5;
    const int wm = wid & 3, wn = wid >> 2;
    const int r = lane >> 2, c = lane & 3;
    const int lr = lane & 15, lc = lane >> 4;

    const __half* gxh = XHp + ((size_t)(bm + (tid >> 2)) * NL + l) * DM + (tid & 3) * 8;
    const __half* gxl = XLp + ((size_t)(bm + (tid >> 2)) * NL + l) * DM + (tid & 3) * 8;
    const uint32_t a_off_t = (uint32_t)(tid >> 2) * ASTR + (uint32_t)(tid & 3) * 8;

    const __half* gwh = WHp + (size_t)l * DM * FL;
    const int brow = tid >> 4, bq = (tid & 15) * 8;
    const uint32_t b_row_off = (uint32_t)brow * BSTR + bq;

    float acc[2][4][4];
#pragma unroll
    for (int mt = 0; mt < 2; mt++)
#pragma unroll
        for (int nt = 0; nt < 4; nt++)
#pragma unroll
            for (int q = 0; q < 4; q++) acc[mt][nt][q] = 0.0f;

#define ENC_ISSUE(KN, ST)                                                        \
    do {                                                                         \
        const uint32_t ao = a_off_t + (uint32_t)(ST) * SA2;                      \
        cp16(sb + 2 * (EXH_BASE + ao), gxh + (KN) * DBK);                        \
        cp16(sb + 2 * (EXL_BASE + ao), gxl + (KN) * DBK);                        \
        const __half* wb = gwh + (size_t)((KN) * DBK + brow) * FL + bn + bq;     \
        cp16(sb + 2 * (EWH_BASE + b_row_off + (uint32_t)(ST) * SB), wb);         \
        asm volatile("cp.async.commit_group;");                                  \
    } while (0)

    ENC_ISSUE(0, 0);
    ENC_ISSUE(1, 1);

    for (int kt = 0; kt < KT; kt++) {
        if (kt + 1 < KT) asm volatile("cp.async.wait_group 1;");
        else             asm volatile("cp.async.wait_group 0;");
        __syncthreads();
        if (kt + 2 < KT) {
            const int kn = kt + 2;
            ENC_ISSUE(kn, kn % 3);
        }
        const int st = kt % 3;
        const uint32_t ah_b = sb + 2 * (EXH_BASE + (uint32_t)st * SA2);
        const uint32_t al_b = sb + 2 * (EXL_BASE + (uint32_t)st * SA2);
        const uint32_t bh_b = sb + 2 * (EWH_BASE + (uint32_t)st * SB);

#pragma unroll
        for (int s = 0; s < 2; s++) {
            uint32_t ah[2][4], bb[2][4];
            const uint32_t aoff = 2 * (uint32_t)((wm * 32 + lr) * ASTR + s * 16 + 8 * lc);
            const uint32_t boff = 2 * (uint32_t)((s * 16 + lr) * BSTR + wn * 32 + 8 * lc);
#pragma unroll
            for (int mt = 0; mt < 2; mt++)
                ldsm_x4(ah[mt], ah_b + aoff + 2 * (uint32_t)(mt * 16 * ASTR));
#pragma unroll
            for (int g = 0; g < 2; g++)
                ldsm_x4t(bb[g], bh_b + boff + 2 * (uint32_t)(g * 16));
#pragma unroll
            for (int mt = 0; mt < 2; mt++)
#pragma unroll
                for (int g = 0; g < 2; g++) {
                    mma_f16(acc[mt][2 * g],     ah[mt], &bb[g][0]);
                    mma_f16(acc[mt][2 * g + 1], ah[mt], &bb[g][2]);
                }
            {
                uint32_t al[2][4];
#pragma unroll
                for (int mt = 0; mt < 2; mt++)
                    ldsm_x4(al[mt], al_b + aoff + 2 * (uint32_t)(mt * 16 * ASTR));
#pragma unroll
                for (int mt = 0; mt < 2; mt++)
#pragma unroll
                    for (int g = 0; g < 2; g++) {
                        mma_f16(acc[mt][2 * g],     al[mt], &bb[g][0]);
                        mma_f16(acc[mt][2 * g + 1], al[mt], &bb[g][2]);
                    }
            }
        }
    }
#undef ENC_ISSUE

    float thr0[4], thr1[4];
#pragma unroll
    for (int nt = 0; nt < 4; nt++) {
        const int col = bn + wn * 32 + nt * 8 + 2 * c;
        thr0[nt] = expf(TH[l * FL + col]);
        thr1[nt] = expf(TH[l * FL + col + 1]);
    }
#pragma unroll
    for (int mt = 0; mt < 2; mt++) {
        const int row = bm + wm * 32 + mt * 16 + r;
#pragma unroll
        for (int nt = 0; nt < 4; nt++) {
            const int col = bn + wn * 32 + nt * 8 + 2 * c;
            const size_t b0 = (size_t)row * (NL * FL) + (size_t)l * FL + col;
            const size_t b1 = b0 + (size_t)8 * (NL * FL);
            const float h0 = acc[mt][nt][0], h1 = acc[mt][nt][1];
            const float h2 = acc[mt][nt][2], h3 = acc[mt][nt][3];
            if (H) {
                *(float2*)(H + b0) = make_float2(h0, h1);
                *(float2*)(H + b1) = make_float2(h2, h3);
            }
            const float a0 = (h0 > thr0[nt]) ? h0 : 0.0f;
            const float a1 = (h1 > thr1[nt]) ? h1 : 0.0f;
            const float a2 = (h2 > thr0[nt]) ? h2 : 0.0f;
            const float a3 = (h3 > thr1[nt]) ? h3 : 0.0f;
            *(float2*)(A + b0) = make_float2(a0, a1);
            *(float2*)(A + b1) = make_float2(a2, a3);
            *(__half2*)(AH16 + b0) = __floats2half2_rn(a0, a1);
            *(__half2*)(AH16 + b1) = __floats2half2_rn(a2, a3);
            if (fabsf(h0 - thr0[nt]) < DELTA) {
                int s0 = atomicAdd(&g_fix_count, 1);
                if (s0 < FIX_CAP) g_fix_list[s0] = (int)b0;
            }
            if (fabsf(h1 - thr1[nt]) < DELTA) {
                int s1 = atomicAdd(&g_fix_count, 1);
                if (s1 < FIX_CAP) g_fix_list[s1] = (int)(b0 + 1);
            }
            if (fabsf(h2 - thr0[nt]) < DELTA) {
                int s2 = atomicAdd(&g_fix_count, 1);
                if (s2 < FIX_CAP) g_fix_list[s2] = (int)b1;
            }
            if (fabsf(h3 - thr1[nt]) < DELTA) {
                int s3 = atomicAdd(&g_fix_count, 1);
                if (s3 < FIX_CAP) g_fix_list[s3] = (int)(b1 + 1);
            }
        }
    }
}

// ---------------- fixup ----------------
__global__ __launch_bounds__(256)
void fixup(const float* __restrict__ x, const float* __restrict__ weT,
           const float* __restrict__ TH, float* __restrict__ A,
           __half* __restrict__ AH16) {
    const int nwarps = gridDim.x * (blockDim.x >> 5);
    const int gw = blockIdx.x * (blockDim.x >> 5) + (threadIdx.x >> 5);
    const int lane = threadIdx.x & 31;
    const int n = min(g_fix_count, FIX_CAP);
    for (int e = gw; e < n; e += nwarps) {
        const int idx = g_fix_list[e];
        const int t = idx / (NL * FL);
        const int rm = idx % (NL * FL);
        const int l = rm / FL, f = rm % FL;
        const float* xr = x + ((size_t)t * NL + l) * DM;
        const float* wr = weT + ((size_t)l * FL + f) * DM;
        float s = 0.0f;
#pragma unroll 4
        for (int d = lane; d < DM; d += 32) s = fmaf(xr[d], wr[d], s);
#pragma unroll
        for (int o = 16; o; o >>= 1) s += __shfl_xor_sync(0xFFFFFFFFu, s, o);
        if (lane == 0) {
            const float thr = expf(TH[l * FL + f]);
            const float a = (s > thr) ? s : 0.0f;
            A[idx] = a;
            AH16[idx] = __float2half_rn(a);
        }
    }
}

// ---------------- decode: CTA 128x128x64, 512 thr, 2/SM ----------------
__global__ __launch_bounds__(512, 2)
void decode_fp16(const __half* __restrict__ AH, const __half* __restrict__ WD,
                 float* __restrict__ XH) {
    extern __shared__ __half sm[];
    const uint32_t sb = smem_u32(sm);

    const int j  = (NL - 1) - blockIdx.z;
    const int bm = blockIdx.y * DM2;
    const int bn = blockIdx.x * DBN;
    const int KT = (j + 1) * (FL / DBK2);   // (j+1)*32

    const int tid  = threadIdx.x;
    const int lane = tid & 31, wid = tid >> 5;
    const int wm = wid & 3, wn = wid >> 2;   // 4m x 4n, warp 32x32
    const int r = lane >> 2, c = lane & 3;
    const int lr = lane & 15, lc = lane >> 4;

    // A: 128 rows x 64 halves = 1024 cp16 -> 2 per thread
    // thread -> row tid>>2, halves [(tid&3)*16, +16)
    const __half* gah = AH + (size_t)(bm + (tid >> 2)) * (NL * FL) + (tid & 3) * 16;
    const uint32_t a_off_t = (uint32_t)(tid >> 2) * ASTR2 + (uint32_t)(tid & 3) * 16;

    // B: 64 rows x 128 halves = 1024 cp16 -> 2 per thread
    // thread -> row tid>>3, halves [(tid&7)*16, +16)
    const __half* wj  = WD + (size_t)j * FL * DM;
    const size_t wd_istride = (size_t)NL * FL * DM;
    const int brow = tid >> 3, bq = (tid & 7) * 16;
    const uint32_t b_row_off = (uint32_t)brow * BSTR + bq;

    float acc[2][4][4];
#pragma unroll
    for (int mt = 0; mt < 2; mt++)
#pragma unroll
        for (int nt = 0; nt < 4; nt++)
#pragma unroll
            for (int q = 0; q < 4; q++) acc[mt][nt][q] = 0.0f;

#define DEC_ISSUE(KN, ST)                                                       \
    do {                                                                        \
        const uint32_t ao = a_off_t + (uint32_t)(ST) * SA2D;                    \
        cp16(sb + 2 * ao,       gah + (KN) * DBK2);                             \
        cp16(sb + 2 * (ao + 8), gah + (KN) * DBK2 + 8);                         \
        const int ii = (KN) >> 5, f0 = ((KN) & 31) * DBK2;                      \
        const __half* sbp = wj + (size_t)ii * wd_istride +                      \
                            (size_t)(f0 + brow) * DM + bn + bq;                 \
        const uint32_t bo = DEC_B_BASE + b_row_off + (uint32_t)(ST) * SBD;      \
        cp16(sb + 2 * bo, sbp);                                                 \
        cp16(sb + 2 * (bo + 8), sbp + 8);                                       \
        asm volatile("cp.async.commit_group;");                                 \
    } while (0)

    DEC_ISSUE(0, 0);
    DEC_ISSUE(1, 1);

    for (int kt = 0; kt < KT; kt++) {
        if (kt + 1 < KT) asm volatile("cp.async.wait_group 1;");
        else             asm volatile("cp.async.wait_group 0;");
        __syncthreads();
        if (kt + 2 < KT) {
            const int kn = kt + 2;
            DEC_ISSUE(kn, kn % 3);
        }
        const int st = kt % 3;
        const uint32_t a_b = sb + 2 * ((uint32_t)st * SA2D);
        const uint32_t b_b = sb + 2 * (DEC_B_BASE + (uint32_t)st * SBD);

#pragma unroll
        for (int s = 0; s < 4; s++) {
            uint32_t a[2][4], bb[2][4];
#pragma unroll
            for (int mt = 0; mt < 2; mt++) {
                const uint32_t ao =
                    2 * ((uint32_t)(wm * 32 + mt * 16 + lr) * ASTR2 + s * 16 + 8 * lc);
                ldsm_x4(a[mt], a_b + ao);
            }
#pragma unroll
            for (int g = 0; g < 2; g++) {
                const uint32_t bo =
                    2 * ((uint32_t)(s * 16 + lr) * BSTR + wn * 32 + g * 16 + 8 * lc);
                ldsm_x4t(bb[g], b_b + bo);
            }
#pragma unroll
            for (int mt = 0; mt < 2; mt++)
#pragma unroll
                for (int g = 0; g < 2; g++) {
                    mma_f16(acc[mt][2 * g],     a[mt], &bb[g][0]);
                    mma_f16(acc[mt][2 * g + 1], a[mt], &bb[g][2]);
                }
        }
    }
#undef DEC_ISSUE

#pragma unroll
    for (int mt = 0; mt < 2; mt++) {
        const int row = bm + wm * 32 + mt * 16 + r;
#pragma unroll
        for (int nt = 0; nt < 4; nt++) {
            const int col = bn + wn * 32 + nt * 8 + 2 * c;
            float* p = XH + (size_t)row * (NL * DM) + (size_t)j * DM + col;
            *(float2*)p = make_float2(acc[mt][nt][0], acc[mt][nt][1]);
            *(float2*)(p + (size_t)8 * (NL * DM)) =
                make_float2(acc[mt][nt][2], acc[mt][nt][3]);
        }
    }
}

// ---------------- host ----------------
extern "C" void kernel_launch(void* const* d_in, const int* in_sizes, int n_in,
                              void* d_out, int out_size) {
    const float* x  = (const float*)d_in[0];
    const float* we = (const float*)d_in[1];
    const float* wd = (const float*)d_in[2];
    const float* th = (const float*)d_in[3];
    float* out = (float*)d_out;

    const long long HE = (long long)T_TOK * NL * FL;
    const long long XE = (long long)T_TOK * NL * DM;

    float *hp, *ap, *xp;
    if ((long long)out_size >= 2 * HE + XE) {
        hp = out; ap = out + HE; xp = out + 2 * HE;
    } else {
        hp = nullptr;
        float* sp = nullptr;
        cudaGetSymbolAddress((void**)&sp, g_acts_scratch);
        ap = sp; xp = out;
    }

    __half *wd16, *ah, *xh, *xl, *weh;
    float* weT;
    cudaGetSymbolAddress((void**)&wd16, g_wd16);
    cudaGetSymbolAddress((void**)&ah, g_ah);
    cudaGetSymbolAddress((void**)&xh, g_xh);
    cudaGetSymbolAddress((void**)&xl, g_xl);
    cudaGetSymbolAddress((void**)&weh, g_weh);
    cudaGetSymbolAddress((void**)&weT, g_weT);

    cudaFuncSetAttribute(decode_fp16, cudaFuncAttributeMaxDynamicSharedMemorySize,
                         SMEM_DEC_BYTES);
    cudaFuncSetAttribute(encode_fused, cudaFuncAttributeMaxDynamicSharedMemorySize,
                         SMEM_ENC_BYTES);

    prep_xwe<<<NB_PREP, 256>>>(x, we, xh, xl, weh, weT);
    encode_fused<<<NWD + ENC_BLOCKS, 512, SMEM_ENC_BYTES>>>(
        xh, xl, weh, th, hp, ap, ah, wd, wd16);
    fixup<<<296, 256>>>(x, weT, th, ap, ah);
    decode_fp16<<<dim3(DM / DBN, T_TOK / DM2, NL), 512, SMEM_DEC_BYTES>>>(ah, wd16, xp);
}

// round 17
// speedup vs baseline: 1.5619x; 1.5619x over previous
#include <cuda_runtime.h>
#include <cuda_fp16.h>
#include <math.h>
#include <stdint.h>

#define T_TOK 2048
#define NL    12
#define DM    768
#define FL    2048

#define DBN 128
#define DBK 32
#define ASTR 40
#define BSTR 136
#define SB (DBK * BSTR)   // 4352 halves per B stage

#define DM2 128
#define SA2 (DM2 * ASTR)  // 5120 halves per A stage

// decode smem (halves): 4 stages
#define DEC_B_BASE (4 * SA2)
#define SMEM_DEC_BYTES ((4 * SA2 + 4 * SB) * 2)         // 75776

// encode smem (halves): XH, XL (3 stages each), WH (3 stages)
#define EXH_BASE 0
#define EXL_BASE (3 * SA2)
#define EWH_BASE (6 * SA2)
#define SMEM_ENC_BYTES ((6 * SA2 + 3 * SB) * 2)         // 87552

#define NWD 78
#define ENC_BLOCKS (16 * 16 * NL)   // 3072

#define FIX_CAP (1 << 22)
#define DELTA 8e-4f

__device__ __half g_wd16[(size_t)NL * NL * FL * DM];
__device__ __half g_ah[(size_t)T_TOK * NL * FL];
__device__ __half g_xh[(size_t)T_TOK * NL * DM];
__device__ __half g_xl[(size_t)T_TOK * NL * DM];
__device__ __half g_weh[(size_t)NL * DM * FL];
__device__ float  g_weT[(size_t)NL * FL * DM];
__device__ float  g_acts_scratch[(size_t)T_TOK * NL * FL];
__device__ int    g_fix_count;
__device__ int    g_fix_list[FIX_CAP];

// ---------------- helpers ----------------
__device__ __forceinline__ uint32_t smem_u32(const void* p) {
    return (uint32_t)__cvta_generic_to_shared(p);
}
__device__ __forceinline__ void cp16(uint32_t d, const void* s) {
    asm volatile("cp.async.cg.shared.global [%0], [%1], 16;" :: "r"(d), "l"(s));
}
__device__ __forceinline__ void ldsm_x4(uint32_t* r, uint32_t a) {
    asm volatile("ldmatrix.sync.aligned.m8n8.x4.shared.b16 {%0,%1,%2,%3}, [%4];"
                 : "=r"(r[0]), "=r"(r[1]), "=r"(r[2]), "=r"(r[3]) : "r"(a));
}
__device__ __forceinline__ void ldsm_x4t(uint32_t* r, uint32_t a) {
    asm volatile("ldmatrix.sync.aligned.m8n8.x4.trans.shared.b16 {%0,%1,%2,%3}, [%4];"
                 : "=r"(r[0]), "=r"(r[1]), "=r"(r[2]), "=r"(r[3]) : "r"(a));
}
__device__ __forceinline__ void mma_f16(float* d, const uint32_t* a, const uint32_t* b) {
    asm volatile(
        "mma.sync.aligned.m16n8k16.row.col.f32.f16.f16.f32 "
        "{%0,%1,%2,%3}, {%4,%5,%6,%7}, {%8,%9}, {%0,%1,%2,%3};"
        : "+f"(d[0]), "+f"(d[1]), "+f"(d[2]), "+f"(d[3])
        : "r"(a[0]), "r"(a[1]), "r"(a[2]), "r"(a[3]), "r"(b[0]), "r"(b[1]));
}
__device__ __forceinline__ void cvt4(__half* h4, float4 v) {
    h4[0] = __float2half_rn(v.x); h4[1] = __float2half_rn(v.y);
    h4[2] = __float2half_rn(v.z); h4[3] = __float2half_rn(v.w);
}

// ---------------- prep ----------------
#define NB_X  (T_TOK * NL * DM / 1024)
#define NB_TR (NL * (DM / 32) * (FL / 32))
#define NB_PREP (2 * NB_X + NB_TR)

__global__ __launch_bounds__(256)
void prep_xwe(const float* __restrict__ x, const float* __restrict__ we,
              __half* __restrict__ xh, __half* __restrict__ xl,
              __half* __restrict__ weh, float* __restrict__ weT) {
    const int b = blockIdx.x;
    if (b == 0 && threadIdx.x == 0) g_fix_count = 0;

    if (b < NB_X) {
        const size_t idx = ((size_t)b * 256 + threadIdx.x) * 4;
        float4 v = *(const float4*)(x + idx);
        __half h4[4]; cvt4(h4, v);
        __half l4[4] = {__float2half_rn(v.x - __half2float(h4[0])),
                        __float2half_rn(v.y - __half2float(h4[1])),
                        __float2half_rn(v.z - __half2float(h4[2])),
                        __float2half_rn(v.w - __half2float(h4[3]))};
        *(uint2*)(xh + idx) = *(uint2*)h4;
        *(uint2*)(xl + idx) = *(uint2*)l4;
    } else if (b < 2 * NB_X) {
        const size_t idx = ((size_t)(b - NB_X) * 256 + threadIdx.x) * 4;
        float4 v = *(const float4*)(we + idx);
        __half h4[4]; cvt4(h4, v);
        *(uint2*)(weh + idx) = *(uint2*)h4;
    } else {
        __shared__ float t[32][33];
        const int bt = b - 2 * NB_X;
        const int l  = bt / ((DM / 32) * (FL / 32));
        const int rm = bt % ((DM / 32) * (FL / 32));
        const int d0 = (rm / (FL / 32)) * 32;
        const int f0 = (rm % (FL / 32)) * 32;
        const int tx = threadIdx.x & 31, ty = threadIdx.x >> 5;
        const float* src = we + (size_t)l * DM * FL;
        float* dst = weT + (size_t)l * FL * DM;
#pragma unroll
        for (int r = 0; r < 32; r += 8)
            t[ty + r][tx] = src[(size_t)(d0 + ty + r) * FL + f0 + tx];
        __syncthreads();
#pragma unroll
        for (int r = 0; r < 32; r += 8)
            dst[(size_t)(f0 + ty + r) * DM + d0 + tx] = t[tx][ty + r];
    }
}

// ---------------- encode: 512 thr, 16 warps, warp 32x32, 2 CTA/SM -----------
__global__ __launch_bounds__(512, 2)
void encode_fused(const __half* __restrict__ XHp, const __half* __restrict__ XLp,
                  const __half* __restrict__ WHp,
                  const float* __restrict__ TH, float* __restrict__ H,
                  float* __restrict__ A, __half* __restrict__ AH16,
                  const float* __restrict__ WDsrc, __half* __restrict__ WD16) {
    if (blockIdx.x < NWD) {
        const int p = blockIdx.x;
        int i = 0, rem = p;
        while (rem >= NL - i) { rem -= NL - i; i++; }
        const size_t zoff = (size_t)(i * NL + i + rem) * FL * DM;
        const float4* src = (const float4*)(WDsrc + zoff);
        uint2* dst = (uint2*)(WD16 + zoff);
        const int N4 = FL * DM / 4;
        for (int q = threadIdx.x; q < N4; q += 1024) {
            float4 v0 = src[q], v1 = src[q + 512];
            __half h0[4], h1[4];
            cvt4(h0, v0); cvt4(h1, v1);
            dst[q]       = *(uint2*)h0;
            dst[q + 512] = *(uint2*)h1;
        }
        return;
    }

    extern __shared__ __half sm[];
    const uint32_t sb = smem_u32(sm);

    const int bid = blockIdx.x - NWD;
    const int l  = bid >> 8;
    const int bm = ((bid >> 4) & 15) * DM2;
    const int bn = (bid & 15) * DBN;
    const int KT = DM / DBK;   // 24

    const int tid  = threadIdx.x;
    const int lane = tid & 31, wid = tid >> 5;
    const int wm = wid & 3, wn = wid >> 2;
    const int r = lane >> 2, c = lane & 3;
    const int lr = lane & 15, lc = lane >> 4;

    const __half* gxh = XHp + ((size_t)(bm + (tid >> 2)) * NL + l) * DM + (tid & 3) * 8;
    const __half* gxl = XLp + ((size_t)(bm + (tid >> 2)) * NL + l) * DM + (tid & 3) * 8;
    const uint32_t a_off_t = (uint32_t)(tid >> 2) * ASTR + (uint32_t)(tid & 3) * 8;

    const __half* gwh = WHp + (size_t)l * DM * FL;
    const int brow = tid >> 4, bq = (tid & 15) * 8;
    const uint32_t b_row_off = (uint32_t)brow * BSTR + bq;

    float acc[2][4][4];
#pragma unroll
    for (int mt = 0; mt < 2; mt++)
#pragma unroll
        for (int nt = 0; nt < 4; nt++)
#pragma unroll
            for (int q = 0; q < 4; q++) acc[mt][nt][q] = 0.0f;

#define ENC_ISSUE(KN, ST)                                                        \
    do {                                                                         \
        const uint32_t ao = a_off_t + (uint32_t)(ST) * SA2;                      \
        cp16(sb + 2 * (EXH_BASE + ao), gxh + (KN) * DBK);                        \
        cp16(sb + 2 * (EXL_BASE + ao), gxl + (KN) * DBK);                        \
        const __half* wb = gwh + (size_t)((KN) * DBK + brow) * FL + bn + bq;     \
        cp16(sb + 2 * (EWH_BASE + b_row_off + (uint32_t)(ST) * SB), wb);         \
        asm volatile("cp.async.commit_group;");                                  \
    } while (0)

    ENC_ISSUE(0, 0);
    ENC_ISSUE(1, 1);

    for (int kt = 0; kt < KT; kt++) {
        if (kt + 1 < KT) asm volatile("cp.async.wait_group 1;");
        else             asm volatile("cp.async.wait_group 0;");
        __syncthreads();
        if (kt + 2 < KT) {
            const int kn = kt + 2;
            ENC_ISSUE(kn, kn % 3);
        }
        const int st = kt % 3;
        const uint32_t ah_b = sb + 2 * (EXH_BASE + (uint32_t)st * SA2);
        const uint32_t al_b = sb + 2 * (EXL_BASE + (uint32_t)st * SA2);
        const uint32_t bh_b = sb + 2 * (EWH_BASE + (uint32_t)st * SB);

#pragma unroll
        for (int s = 0; s < 2; s++) {
            uint32_t ah[2][4], bb[2][4];
            const uint32_t aoff = 2 * (uint32_t)((wm * 32 + lr) * ASTR + s * 16 + 8 * lc);
            const uint32_t boff = 2 * (uint32_t)((s * 16 + lr) * BSTR + wn * 32 + 8 * lc);
#pragma unroll
            for (int mt = 0; mt < 2; mt++)
                ldsm_x4(ah[mt], ah_b + aoff + 2 * (uint32_t)(mt * 16 * ASTR));
#pragma unroll
            for (int g = 0; g < 2; g++)
                ldsm_x4t(bb[g], bh_b + boff + 2 * (uint32_t)(g * 16));
#pragma unroll
            for (int mt = 0; mt < 2; mt++)
#pragma unroll
                for (int g = 0; g < 2; g++) {
                    mma_f16(acc[mt][2 * g],     ah[mt], &bb[g][0]);
                    mma_f16(acc[mt][2 * g + 1], ah[mt], &bb[g][2]);
                }
            {
                uint32_t al[2][4];
#pragma unroll
                for (int mt = 0; mt < 2; mt++)
                    ldsm_x4(al[mt], al_b + aoff + 2 * (uint32_t)(mt * 16 * ASTR));
#pragma unroll
                for (int mt = 0; mt < 2; mt++)
#pragma unroll
                    for (int g = 0; g < 2; g++) {
                        mma_f16(acc[mt][2 * g],     al[mt], &bb[g][0]);
                        mma_f16(acc[mt][2 * g + 1], al[mt], &bb[g][2]);
                    }
            }
        }
    }
#undef ENC_ISSUE

    float thr0[4], thr1[4];
#pragma unroll
    for (int nt = 0; nt < 4; nt++) {
        const int col = bn + wn * 32 + nt * 8 + 2 * c;
        thr0[nt] = expf(TH[l * FL + col]);
        thr1[nt] = expf(TH[l * FL + col + 1]);
    }
#pragma unroll
    for (int mt = 0; mt < 2; mt++) {
        const int row = bm + wm * 32 + mt * 16 + r;
#pragma unroll
        for (int nt = 0; nt < 4; nt++) {
            const int col = bn + wn * 32 + nt * 8 + 2 * c;
            const size_t b0 = (size_t)row * (NL * FL) + (size_t)l * FL + col;
            const size_t b1 = b0 + (size_t)8 * (NL * FL);
            const float h0 = acc[mt][nt][0], h1 = acc[mt][nt][1];
            const float h2 = acc[mt][nt][2], h3 = acc[mt][nt][3];
            if (H) {
                *(float2*)(H + b0) = make_float2(h0, h1);
                *(float2*)(H + b1) = make_float2(h2, h3);
            }
            const float a0 = (h0 > thr0[nt]) ? h0 : 0.0f;
            const float a1 = (h1 > thr1[nt]) ? h1 : 0.0f;
            const float a2 = (h2 > thr0[nt]) ? h2 : 0.0f;
            const float a3 = (h3 > thr1[nt]) ? h3 : 0.0f;
            *(float2*)(A + b0) = make_float2(a0, a1);
            *(float2*)(A + b1) = make_float2(a2, a3);
            *(__half2*)(AH16 + b0) = __floats2half2_rn(a0, a1);
            *(__half2*)(AH16 + b1) = __floats2half2_rn(a2, a3);
            if (fabsf(h0 - thr0[nt]) < DELTA) {
                int s0 = atomicAdd(&g_fix_count, 1);
                if (s0 < FIX_CAP) g_fix_list[s0] = (int)b0;
            }
            if (fabsf(h1 - thr1[nt]) < DELTA) {
                int s1 = atomicAdd(&g_fix_count, 1);
                if (s1 < FIX_CAP) g_fix_list[s1] = (int)(b0 + 1);
            }
            if (fabsf(h2 - thr0[nt]) < DELTA) {
                int s2 = atomicAdd(&g_fix_count, 1);
                if (s2 < FIX_CAP) g_fix_list[s2] = (int)b1;
            }
            if (fabsf(h3 - thr1[nt]) < DELTA) {
                int s3 = atomicAdd(&g_fix_count, 1);
                if (s3 < FIX_CAP) g_fix_list[s3] = (int)(b1 + 1);
            }
        }
    }
}

// ---------------- fixup ----------------
__global__ __launch_bounds__(256)
void fixup(const float* __restrict__ x, const float* __restrict__ weT,
           const float* __restrict__ TH, float* __restrict__ A,
           __half* __restrict__ AH16) {
    const int nwarps = gridDim.x * (blockDim.x >> 5);
    const int gw = blockIdx.x * (blockDim.x >> 5) + (threadIdx.x >> 5);
    const int lane = threadIdx.x & 31;
    const int n = min(g_fix_count, FIX_CAP);
    for (int e = gw; e < n; e += nwarps) {
        const int idx = g_fix_list[e];
        const int t = idx / (NL * FL);
        const int rm = idx % (NL * FL);
        const int l = rm / FL, f = rm % FL;
        const float* xr = x + ((size_t)t * NL + l) * DM;
        const float* wr = weT + ((size_t)l * FL + f) * DM;
        float s = 0.0f;
#pragma unroll 4
        for (int d = lane; d < DM; d += 32) s = fmaf(xr[d], wr[d], s);
#pragma unroll
        for (int o = 16; o; o >>= 1) s += __shfl_xor_sync(0xFFFFFFFFu, s, o);
        if (lane == 0) {
            const float thr = expf(TH[l * FL + f]);
            const float a = (s > thr) ? s : 0.0f;
            A[idx] = a;
            AH16[idx] = __float2half_rn(a);
        }
    }
}

// ---------------- decode: CTA 128x128x32, 512 thr, 4-stage pipe, 2/SM -------
__global__ __launch_bounds__(512, 2)
void decode_fp16(const __half* __restrict__ AH, const __half* __restrict__ WD,
                 float* __restrict__ XH) {
    extern __shared__ __half sm[];
    const uint32_t sb = smem_u32(sm);

    const int j  = (NL - 1) - blockIdx.z;
    const int bm = blockIdx.y * DM2;
    const int bn = blockIdx.x * DBN;
    const int KT = (j + 1) * (FL / DBK);

    const int tid  = threadIdx.x;
    const int lane = tid & 31, wid = tid >> 5;
    const int wm = wid & 3, wn = wid >> 2;
    const int r = lane >> 2, c = lane & 3;
    const int lr = lane & 15, lc = lane >> 4;

    const __half* gah = AH + (size_t)(bm + (tid >> 2)) * (NL * FL) + (tid & 3) * 8;
    const uint32_t a_off_t = (uint32_t)(tid >> 2) * ASTR + (uint32_t)(tid & 3) * 8;

    const __half* wj  = WD + (size_t)j * FL * DM;
    const size_t wd_istride = (size_t)NL * FL * DM;
    const int brow = tid >> 4, bq = (tid & 15) * 8;
    const uint32_t b_row_off = (uint32_t)brow * BSTR + bq;

    float acc[2][4][4];
#pragma unroll
    for (int mt = 0; mt < 2; mt++)
#pragma unroll
        for (int nt = 0; nt < 4; nt++)
#pragma unroll
            for (int q = 0; q < 4; q++) acc[mt][nt][q] = 0.0f;

#define DEC_ISSUE(KN, ST)                                                       \
    do {                                                                        \
        cp16(sb + 2 * (a_off_t + (uint32_t)(ST) * SA2), gah + (KN) * DBK);      \
        const int ii = (KN) >> 6, f0 = ((KN) & 63) * DBK;                       \
        const __half* sbp = wj + (size_t)ii * wd_istride +                      \
                            (size_t)(f0 + brow) * DM + bn + bq;                 \
        cp16(sb + 2 * (DEC_B_BASE + b_row_off + (uint32_t)(ST) * SB), sbp);     \
        asm volatile("cp.async.commit_group;");                                 \
    } while (0)

    DEC_ISSUE(0, 0);
    DEC_ISSUE(1, 1);
    if (KT > 2) DEC_ISSUE(2, 2);

    for (int kt = 0; kt < KT; kt++) {
        if (kt + 3 <= KT)      asm volatile("cp.async.wait_group 2;");
        else if (kt + 2 == KT) asm volatile("cp.async.wait_group 1;");
        else                   asm volatile("cp.async.wait_group 0;");
        __syncthreads();
        if (kt + 3 < KT) {
            const int kn = kt + 3;
            DEC_ISSUE(kn, kn & 3);
        }
        const int st = kt & 3;
        const uint32_t a_b = sb + 2 * ((uint32_t)st * SA2);
        const uint32_t b_b = sb + 2 * (DEC_B_BASE + (uint32_t)st * SB);

#pragma unroll
        for (int s = 0; s < 2; s++) {
            uint32_t a[2][4], bb[2][4];
#pragma unroll
            for (int mt = 0; mt < 2; mt++) {
                const uint32_t ao =
                    2 * ((uint32_t)(wm * 32 + mt * 16 + lr) * ASTR + s * 16 + 8 * lc);
                ldsm_x4(a[mt], a_b + ao);
            }
#pragma unroll
            for (int g = 0; g < 2; g++) {
                const uint32_t bo =
                    2 * ((uint32_t)(s * 16 + lr) * BSTR + wn * 32 + g * 16 + 8 * lc);
                ldsm_x4t(bb[g], b_b + bo);
            }
#pragma unroll
            for (int mt = 0; mt < 2; mt++)
#pragma unroll
                for (int g = 0; g < 2; g++) {
                    mma_f16(acc[mt][2 * g],     a[mt], &bb[g][0]);
                    mma_f16(acc[mt][2 * g + 1], a[mt], &bb[g][2]);
                }
        }
    }
#undef DEC_ISSUE

#pragma unroll
    for (int mt = 0; mt < 2; mt++) {
        const int row = bm + wm * 32 + mt * 16 + r;
#pragma unroll
        for (int nt = 0; nt < 4; nt++) {
            const int col = bn + wn * 32 + nt * 8 + 2 * c;
            float* p = XH + (size_t)row * (NL * DM) + (size_t)j * DM + col;
            *(float2*)p = make_float2(acc[mt][nt][0], acc[mt][nt][1]);
            *(float2*)(p + (size_t)8 * (NL * DM)) =
                make_float2(acc[mt][nt][2], acc[mt][nt][3]);
        }
    }
}

// ---------------- host ----------------
extern "C" void kernel_launch(void* const* d_in, const int* in_sizes, int n_in,
                              void* d_out, int out_size) {
    const float* x  = (const float*)d_in[0];
    const float* we = (const float*)d_in[1];
    const float* wd = (const float*)d_in[2];
    const float* th = (const float*)d_in[3];
    float* out = (float*)d_out;

    const long long HE = (long long)T_TOK * NL * FL;
    const long long XE = (long long)T_TOK * NL * DM;

    float *hp, *ap, *xp;
    if ((long long)out_size >= 2 * HE + XE) {
        hp = out; ap = out + HE; xp = out + 2 * HE;
    } else {
        hp = nullptr;
        float* sp = nullptr;
        cudaGetSymbolAddress((void**)&sp, g_acts_scratch);
        ap = sp; xp = out;
    }

    __half *wd16, *ah, *xh, *xl, *weh;
    float* weT;
    cudaGetSymbolAddress((void**)&wd16, g_wd16);
    cudaGetSymbolAddress((void**)&ah, g_ah);
    cudaGetSymbolAddress((void**)&xh, g_xh);
    cudaGetSymbolAddress((void**)&xl, g_xl);
    cudaGetSymbolAddress((void**)&weh, g_weh);
    cudaGetSymbolAddress((void**)&weT, g_weT);

    cudaFuncSetAttribute(decode_fp16, cudaFuncAttributeMaxDynamicSharedMemorySize,
                         SMEM_DEC_BYTES);
    cudaFuncSetAttribute(encode_fused, cudaFuncAttributeMaxDynamicSharedMemorySize,
                         SMEM_ENC_BYTES);

    prep_xwe<<<NB_PREP, 256>>>(x, we, xh, xl, weh, weT);
    encode_fused<<<NWD + ENC_BLOCKS, 512, SMEM_ENC_BYTES>>>(
        xh, xl, weh, th, hp, ap, ah, wd, wd16);
    fixup<<<296, 256>>>(x, weT, th, ap, ah);
    decode_fp16<<<dim3(DM / DBN, T_TOK / DM2, NL), 512, SMEM_DEC_BYTES>>>(ah, wd16, xp);
}